// round 1
// baseline (speedup 1.0000x reference)
#include <cuda_runtime.h>

#define NB 4096
#define L 64
#define D 128
#define TMAX 65   // counts are in [0, 64]

// Lookup table: T[a][e] = sum_d relu(a*W1[d]+b1[d]) * W2[d][e] + b2[e]
__device__ float g_T[TMAX * D];

__global__ __launch_bounds__(D) void build_table_kernel(
    const float* __restrict__ W1, const float* __restrict__ b1,
    const float* __restrict__ W2, const float* __restrict__ b2)
{
    __shared__ float h[D];
    const int a = blockIdx.x;      // 0..64
    const int e = threadIdx.x;     // 0..127
    h[e] = fmaxf((float)a * W1[e] + b1[e], 0.0f);
    __syncthreads();
    float acc = b2[e];
    #pragma unroll 8
    for (int d = 0; d < D; ++d)
        acc = fmaf(h[d], W2[d * D + e], acc);
    g_T[a * D + e] = acc;
}

__global__ __launch_bounds__(128) void nif_encoder_kernel(
    const int* __restrict__ src_ids, const int* __restrict__ dst_ids,
    const int* __restrict__ src_nb,  const int* __restrict__ dst_nb,
    float* __restrict__ out)
{
    __shared__ float sT[TMAX * D];        // 33280 B
    __shared__ int   s_src[L], s_dst[L];
    __shared__ int   s_a0[2 * L], s_a1[2 * L];
    __shared__ int   s_cd, s_cs;

    const int b   = blockIdx.x;
    const int tid = threadIdx.x;

    // Stage the lookup table (L2-resident after first wave)
    #pragma unroll
    for (int i = tid; i < TMAX * D; i += 128) sT[i] = g_T[i];

    if (tid < L)  s_src[tid]     = src_nb[b * L + tid];
    else          s_dst[tid - L] = dst_nb[b * L + (tid - L)];
    if (tid == 0) { s_cd = 0; s_cs = 0; }
    __syncthreads();

    const int sid = src_ids[b];
    const int did = dst_ids[b];

    // cd = count(src_id in dst list), cs = count(dst_id in src list)
    if (tid < L)  { if (s_dst[tid]     == sid) atomicAdd(&s_cd, 1); }
    else          { if (s_src[tid - L] == did) atomicAdd(&s_cs, 1); }
    __syncthreads();

    const int  cd      = s_cd;
    const int  cs      = s_cs;
    const bool same    = (sid == did);
    const bool in_dst  = (cd > 0);               // srcid_in_dst
    const bool cond2   = (cs > 0) || (same && in_dst);
    const int  v2      = (same && in_dst) ? cd : cs;

    // Per-neighbor counts + dict-mutation overrides (exact reference semantics)
    if (tid < L) {
        const int x = s_src[tid];
        int c_self = 0, c_cross = 0;
        #pragma unroll
        for (int j = 0; j < L; ++j) {
            c_self  += (x == s_src[j]);
            c_cross += (x == s_dst[j]);
        }
        s_a0[tid] = c_self;                                   // c_src
        s_a1[tid] = (x == did && cond2) ? v2 : c_cross;       // src_col1
    } else {
        const int i = tid - L;
        const int y = s_dst[i];
        int c_cross = 0, c_self = 0;
        #pragma unroll
        for (int j = 0; j < L; ++j) {
            c_cross += (y == s_src[j]);
            c_self  += (y == s_dst[j]);
        }
        s_a0[tid] = (y == sid && in_dst) ? cd : c_cross;      // dst_col0
        s_a1[tid] = c_self;                                   // c_dst
    }
    __syncthreads();

    // Emit 128 rows (64 src + 64 dst), out[row] = T[a0] + T[a1].
    // One warp per row, float4 per lane (512 B per row, fully coalesced).
    const int lane = tid & 31;
    const int wrp  = tid >> 5;
    const size_t half   = (size_t)NB * L * D;
    float* out_src = out + (size_t)b * L * D;
    float* out_dst = out + half + (size_t)b * L * D;

    #pragma unroll 4
    for (int it = 0; it < 32; ++it) {
        const int r  = it * 4 + wrp;
        const int a0 = s_a0[r];
        const int a1 = s_a1[r];
        const float4 t0 = *(const float4*)&sT[a0 * D + lane * 4];
        const float4 t1 = *(const float4*)&sT[a1 * D + lane * 4];
        float4 o;
        o.x = t0.x + t1.x; o.y = t0.y + t1.y;
        o.z = t0.z + t1.z; o.w = t0.w + t1.w;
        float* dst_row = (r < L) ? (out_src + r * D) : (out_dst + (r - L) * D);
        *(float4*)&dst_row[lane * 4] = o;
    }
}

extern "C" void kernel_launch(void* const* d_in, const int* in_sizes, int n_in,
                              void* d_out, int out_size)
{
    const int*   src_ids = (const int*)  d_in[0];
    const int*   dst_ids = (const int*)  d_in[1];
    const int*   src_nb  = (const int*)  d_in[2];
    const int*   dst_nb  = (const int*)  d_in[3];
    const float* W1      = (const float*)d_in[4];
    const float* b1      = (const float*)d_in[5];
    const float* W2      = (const float*)d_in[6];
    const float* b2      = (const float*)d_in[7];
    float*       out     = (float*)d_out;

    build_table_kernel<<<TMAX, D>>>(W1, b1, W2, b2);
    nif_encoder_kernel<<<NB, 128>>>(src_ids, dst_ids, src_nb, dst_nb, out);
}

// round 2
// speedup vs baseline: 1.2667x; 1.2667x over previous
#include <cuda_runtime.h>

#define NB 4096
#define L 64
#define D 128
#define TMAX 65            // counts are in [0, 64]
#define GRID 512           // 4096 / 512 = 8 batches per block, uniform
#define THREADS 256

// Lookup table: T[a][e] = sum_d relu(a*W1[d]+b1[d]) * W2[d][e] + b2[e]
__device__ float g_T[TMAX * D];

__global__ __launch_bounds__(D) void build_table_kernel(
    const float* __restrict__ W1, const float* __restrict__ b1,
    const float* __restrict__ W2, const float* __restrict__ b2)
{
    __shared__ float h[D];
    const int a = blockIdx.x;      // 0..64
    const int e = threadIdx.x;     // 0..127
    h[e] = fmaxf((float)a * W1[e] + b1[e], 0.0f);
    __syncthreads();
    float acc = b2[e];
    #pragma unroll 8
    for (int d = 0; d < D; ++d)
        acc = fmaf(h[d], W2[d * D + e], acc);
    g_T[a * D + e] = acc;
}

__global__ __launch_bounds__(THREADS) void nif_encoder_kernel(
    const int* __restrict__ src_ids, const int* __restrict__ dst_ids,
    const int* __restrict__ src_nb,  const int* __restrict__ dst_nb,
    float* __restrict__ out)
{
    __shared__ float sT[TMAX * D];          // 33280 B, staged ONCE per block
    __shared__ int   s_src[L], s_dst[L];
    __shared__ int   s_a0[2 * L], s_a1[2 * L];
    __shared__ int   s_cd, s_cs;

    const int tid  = threadIdx.x;
    const int lane = tid & 31;
    const int wrp  = tid >> 5;              // 0..7
    const size_t half = (size_t)NB * L * D;

    // Stage the lookup table once (L2-resident; 512 blocks x 33KB = 17MB L2 reads)
    #pragma unroll
    for (int i = tid; i < TMAX * D; i += THREADS) sT[i] = g_T[i];

    for (int b = blockIdx.x; b < NB; b += GRID) {
        // ---- load neighbor lists + reset counters ----
        if (tid < L)            s_src[tid]       = __ldg(&src_nb[b * L + tid]);
        else if (tid < 2 * L)   s_dst[tid - L]   = __ldg(&dst_nb[b * L + (tid - L)]);
        if (tid == 0) { s_cd = 0; s_cs = 0; }
        __syncthreads();

        const int sid = __ldg(&src_ids[b]);
        const int did = __ldg(&dst_ids[b]);

        // ---- cd = count(src_id in dst list), cs = count(dst_id in src list)
        //      plus per-neighbor self/cross counts (independent of cd/cs) ----
        int c_self = 0, c_other = 0, my_x = 0;
        if (tid < L) {
            if (s_dst[tid] == sid) atomicAdd(&s_cd, 1);
            my_x = s_src[tid];
            #pragma unroll
            for (int j = 0; j < L; ++j) {
                c_self  += (my_x == s_src[j]);
                c_other += (my_x == s_dst[j]);   // count of src-nb in dst list
            }
        } else if (tid < 2 * L) {
            const int i = tid - L;
            if (s_src[i] == did) atomicAdd(&s_cs, 1);
            my_x = s_dst[i];
            #pragma unroll
            for (int j = 0; j < L; ++j) {
                c_self  += (my_x == s_dst[j]);
                c_other += (my_x == s_src[j]);   // count of dst-nb in src list
            }
        }
        __syncthreads();

        // ---- apply dict-mutation overrides (exact reference semantics) ----
        if (tid < 2 * L) {
            const int  cd     = s_cd;
            const int  cs     = s_cs;
            const bool same   = (sid == did);
            const bool in_dst = (cd > 0);                      // srcid_in_dst
            const bool cond2  = (cs > 0) || (same && in_dst);
            const int  v2     = (same && in_dst) ? cd : cs;
            if (tid < L) {
                s_a0[tid] = c_self;                                      // c_src
                s_a1[tid] = (my_x == did && cond2)  ? v2 : c_other;      // src_col1
            } else {
                s_a0[tid] = (my_x == sid && in_dst) ? cd : c_other;      // dst_col0
                s_a1[tid] = c_self;                                      // c_dst
            }
        }
        __syncthreads();

        // ---- emit 128 rows: out[row] = T[a0] + T[a1], streaming float4 stores
        float* out_src = out + (size_t)b * L * D;
        float* out_dst = out + half + (size_t)b * L * D;

        #pragma unroll 4
        for (int it = 0; it < 16; ++it) {
            const int r  = it * 8 + wrp;
            const int a0 = s_a0[r];
            const int a1 = s_a1[r];
            const float4 t0 = *(const float4*)&sT[a0 * D + lane * 4];
            const float4 t1 = *(const float4*)&sT[a1 * D + lane * 4];
            float4 o;
            o.x = t0.x + t1.x; o.y = t0.y + t1.y;
            o.z = t0.z + t1.z; o.w = t0.w + t1.w;
            float* dst_row = (r < L) ? (out_src + r * D) : (out_dst + (r - L) * D);
            __stcs((float4*)&dst_row[lane * 4], o);
        }
        __syncthreads();   // protect s_* reuse for next batch
    }
}

extern "C" void kernel_launch(void* const* d_in, const int* in_sizes, int n_in,
                              void* d_out, int out_size)
{
    const int*   src_ids = (const int*)  d_in[0];
    const int*   dst_ids = (const int*)  d_in[1];
    const int*   src_nb  = (const int*)  d_in[2];
    const int*   dst_nb  = (const int*)  d_in[3];
    const float* W1      = (const float*)d_in[4];
    const float* b1      = (const float*)d_in[5];
    const float* W2      = (const float*)d_in[6];
    const float* b2      = (const float*)d_in[7];
    float*       out     = (float*)d_out;

    build_table_kernel<<<TMAX, D>>>(W1, b1, W2, b2);
    nif_encoder_kernel<<<GRID, THREADS>>>(src_ids, dst_ids, src_nb, dst_nb, out);
}